// round 11
// baseline (speedup 1.0000x reference)
#include <cuda_runtime.h>
#include <cstdint>

// UniformShardedEmbeddingBags: B=1024, T=32, D=64, E=100000, L=50
// out[bag, :] = sum_{j<50} W[feat[bag*50 + j], bag % 32, :]
//
// R11 = R7 body (harness-best, 59.39us) with 512-thread CTAs (2048 blocks,
// 16 warps/CTA; 4 CTAs/SM at 32 regs keeps occupancy unchanged). Last
// untested point on the CTA-size axis, which showed a tiny monotone trend
// (128 < 256). Fewer CTAs -> fewer CLC scheduling/retire events per wave.
//
// Final design (established R2..R10):
//  - one bag per warp; 32 lanes x float2 = 256B fully-coalesced per row;
//    fully-unrolled 25x LDG.64 gather (R6: persistent loop breaks ptxas
//    LDG front-batching); 32-reg budget (R4: regs>32 costs occupancy).
//  - table-grouped bag order: warps [t*1024,(t+1)*1024) pool table t, so
//    ~9 table slices (~94MB) stay L2-resident and all ~22% duplicate draws
//    hit L2 -> DRAM traffic at the compulsory ~348MB floor.
//  - __stcs output; plain cached index loads (R5).
//  - Achieved ~5.9TB/s is the random-256B-burst controller ceiling; the
//    remaining gap to spec BW is not addressable from the SM side.
//  - Measurement: harness is stable (sigma ~0.1us); ncu DRAM%/dur vary
//    +/-2.5us run-to-run on identical binaries (R8 vs R10).

namespace {
constexpr int kT = 32;
constexpr int kD = 64;
constexpr int kL = 50;
constexpr int kNumBags = 1024 * kT;                  // 32768
constexpr int kThreads = 512;                        // 16 warps / block
constexpr int kBlocks = kNumBags / (kThreads / 32);  // 2048
}  // namespace

__global__ __launch_bounds__(kThreads)
void embedding_bag_kernel(const float* __restrict__ weights,
                          const int* __restrict__ features,
                          float* __restrict__ out) {
    const int w = (blockIdx.x * kThreads + threadIdx.x) >> 5;
    const int lane = threadIdx.x & 31;

    // Table-grouped remap: warps [t*1024, (t+1)*1024) all pool table t.
    const int bag = ((w & 1023) << 5) | (w >> 10);
    const int table = w >> 10;  // == bag & 31

    const int* __restrict__ idxp = features + bag * kL;

    // Coalesced index fetch: lane j holds draw j; lanes 0..17 also draw 32+j.
    const int i0 = __ldg(idxp + lane);
    const int i1 = (lane < kL - 32) ? __ldg(idxp + 32 + lane) : 0;

    // Base pointer into this bag's table slice, as float2.
    const float2* __restrict__ base =
        reinterpret_cast<const float2*>(weights) + (size_t)table * (kD / 2);
    constexpr size_t kRowStride2 = (size_t)kT * kD / 2;  // 1024 float2 per e

    float2 acc0 = make_float2(0.f, 0.f);
    float2 acc1 = make_float2(0.f, 0.f);

#pragma unroll
    for (int k = 0; k < 32; k += 2) {
        const int ia = __shfl_sync(0xffffffffu, i0, k);
        const int ib = __shfl_sync(0xffffffffu, i0, k + 1);
        const float2 va = __ldg(base + (size_t)ia * kRowStride2 + lane);
        const float2 vb = __ldg(base + (size_t)ib * kRowStride2 + lane);
        acc0.x += va.x; acc0.y += va.y;
        acc1.x += vb.x; acc1.y += vb.y;
    }
#pragma unroll
    for (int k = 0; k < 18; k += 2) {
        const int ia = __shfl_sync(0xffffffffu, i1, k);
        const int ib = __shfl_sync(0xffffffffu, i1, k + 1);
        const float2 va = __ldg(base + (size_t)ia * kRowStride2 + lane);
        const float2 vb = __ldg(base + (size_t)ib * kRowStride2 + lane);
        acc0.x += va.x; acc0.y += va.y;
        acc1.x += vb.x; acc1.y += vb.y;
    }

    float2 r;
    r.x = acc0.x + acc1.x;
    r.y = acc0.y + acc1.y;
    __stcs(reinterpret_cast<float2*>(out) + (size_t)bag * (kD / 2) + lane, r);
}

extern "C" void kernel_launch(void* const* d_in, const int* in_sizes, int n_in,
                              void* d_out, int out_size) {
    const float* weights  = (const float*)d_in[0];   // (E, T, D) fp32
    const int*   features = (const int*)d_in[1];     // (B*T*L,) int32
    // d_in[2]: offsets — uniform arange*L, folded into compile-time constants.
    float* out = (float*)d_out;                      // (B, T, D) fp32

    embedding_bag_kernel<<<kBlocks, kThreads>>>(weights, features, out);
}

// round 12
// speedup vs baseline: 1.0243x; 1.0243x over previous
#include <cuda_runtime.h>
#include <cstdint>

// UniformShardedEmbeddingBags: B=1024, T=32, D=64, E=100000, L=50
// out[bag, :] = sum_{j<50} W[feat[bag*50 + j], bag % 32, :]
//
// FINAL (R12 = R7, the harness-best configuration at 59.39us; all axes
// explored R2..R11, kernel is at the random-gather HBM ceiling):
//  - one bag per warp; 32 lanes x float2 = 256B fully-coalesced per row
//    (rows are 256B-aligned -> zero over-fetch); fully-unrolled 25x LDG.64
//    gather with shfl-broadcast indices (one-shot grid — R6 showed a
//    persistent loop breaks ptxas LDG front-batching).
//  - 32-reg budget / occ ~90% (R4: regs>32 costs occupancy and DRAM util).
//  - table-grouped bag order: warps [t*1024,(t+1)*1024) pool table t, so
//    ~9 table slices (~94MB) stay L2-resident and the ~22% duplicate draws
//    all hit L2 -> DRAM traffic at the compulsory ~348MB floor (R2: the
//    single structural win, 65.7 -> 59.4us).
//  - __stcs output so 8MB of writes don't evict gather lines; plain cached
//    index loads (R5: streaming hints on shared index lines hurt).
//  - Achieved ~5.9TB/s (73-76% of spec) is the controller-efficiency
//    ceiling for random 256B bursts over an 819MB footprint; CTA size
//    (128/256/512), index vector width, and cache hints are all flat
//    within the harness noise band (sigma ~0.07us).

namespace {
constexpr int kT = 32;
constexpr int kD = 64;
constexpr int kL = 50;
constexpr int kNumBags = 1024 * kT;                  // 32768
constexpr int kThreads = 256;                        // 8 warps / block
constexpr int kBlocks = kNumBags / (kThreads / 32);  // 4096
}  // namespace

__global__ __launch_bounds__(kThreads)
void embedding_bag_kernel(const float* __restrict__ weights,
                          const int* __restrict__ features,
                          float* __restrict__ out) {
    const int w = (blockIdx.x * kThreads + threadIdx.x) >> 5;
    const int lane = threadIdx.x & 31;

    // Table-grouped remap: warps [t*1024, (t+1)*1024) all pool table t.
    const int bag = ((w & 1023) << 5) | (w >> 10);
    const int table = w >> 10;  // == bag & 31

    const int* __restrict__ idxp = features + bag * kL;

    // Coalesced index fetch: lane j holds draw j; lanes 0..17 also draw 32+j.
    const int i0 = __ldg(idxp + lane);
    const int i1 = (lane < kL - 32) ? __ldg(idxp + 32 + lane) : 0;

    // Base pointer into this bag's table slice, as float2.
    const float2* __restrict__ base =
        reinterpret_cast<const float2*>(weights) + (size_t)table * (kD / 2);
    constexpr size_t kRowStride2 = (size_t)kT * kD / 2;  // 1024 float2 per e

    float2 acc0 = make_float2(0.f, 0.f);
    float2 acc1 = make_float2(0.f, 0.f);

#pragma unroll
    for (int k = 0; k < 32; k += 2) {
        const int ia = __shfl_sync(0xffffffffu, i0, k);
        const int ib = __shfl_sync(0xffffffffu, i0, k + 1);
        const float2 va = __ldg(base + (size_t)ia * kRowStride2 + lane);
        const float2 vb = __ldg(base + (size_t)ib * kRowStride2 + lane);
        acc0.x += va.x; acc0.y += va.y;
        acc1.x += vb.x; acc1.y += vb.y;
    }
#pragma unroll
    for (int k = 0; k < 18; k += 2) {
        const int ia = __shfl_sync(0xffffffffu, i1, k);
        const int ib = __shfl_sync(0xffffffffu, i1, k + 1);
        const float2 va = __ldg(base + (size_t)ia * kRowStride2 + lane);
        const float2 vb = __ldg(base + (size_t)ib * kRowStride2 + lane);
        acc0.x += va.x; acc0.y += va.y;
        acc1.x += vb.x; acc1.y += vb.y;
    }

    float2 r;
    r.x = acc0.x + acc1.x;
    r.y = acc0.y + acc1.y;
    __stcs(reinterpret_cast<float2*>(out) + (size_t)bag * (kD / 2) + lane, r);
}

extern "C" void kernel_launch(void* const* d_in, const int* in_sizes, int n_in,
                              void* d_out, int out_size) {
    const float* weights  = (const float*)d_in[0];   // (E, T, D) fp32
    const int*   features = (const int*)d_in[1];     // (B*T*L,) int32
    // d_in[2]: offsets — uniform arange*L, folded into compile-time constants.
    float* out = (float*)d_out;                      // (B, T, D) fp32

    embedding_bag_kernel<<<kBlocks, kThreads>>>(weights, features, out);
}

// round 14
// speedup vs baseline: 1.0277x; 1.0033x over previous
#include <cuda_runtime.h>
#include <cstdint>

// UniformShardedEmbeddingBags: B=1024, T=32, D=64, E=100000, L=50
// out[bag, :] = sum_{j<50} W[feat[bag*50 + j], bag % 32, :]
//
// R14 = R7/R12 body (harness-best 58.0-59.4us across holds) + L2 evict-last
// policy on the row gathers, encoded legally for sm_103a this time:
// createpolicy.fractional.L2::evict_last.b64 (uniform, expected to live in
// a UR) + ld.global.nc.L2::cache_hint.v2.f32. (R13 lesson: bare
// .L2::evict_last qualifiers are restricted to 256-bit loads on sm_103a.)
// Goal: keep first-touch embedding lines resident until their duplicate
// draw arrives — measured L2 hit ~20% vs theoretical ~22% dupe rate; the
// residual ~8MB of early-evicted dupes is the last removable DRAM traffic.
//
// Established invariants (R2..R12):
//  - one bag per warp; float2/LDG.64 coalesced 256B rows; fully-unrolled
//    (R6: loops break ptxas LDG front-batching); 32-reg budget, pinned via
//    __launch_bounds__(256, 8) (R4: regs>32 costs occupancy + DRAM util).
//  - table-grouped bag order: ~9 table slices (~94MB) L2-resident; DRAM
//    traffic at the compulsory ~348MB floor (R2, the structural win).
//  - __stcs output; plain cached index loads (R5).
//  - ~5.9-6.0 TB/s = random-256B controller ceiling; CTA size flat;
//    cross-hold harness variance ~±1.4us (R12 vs R7, same binary).

namespace {
constexpr int kT = 32;
constexpr int kD = 64;
constexpr int kL = 50;
constexpr int kNumBags = 1024 * kT;                  // 32768
constexpr int kThreads = 256;                        // 8 warps / block
constexpr int kBlocks = kNumBags / (kThreads / 32);  // 4096
}  // namespace

// float2 gather carrying an L2 evict-last cache policy.
static __device__ __forceinline__ float2 ldg_policy_f2(const float2* p,
                                                       uint64_t pol) {
    float2 v;
    asm volatile("ld.global.nc.L2::cache_hint.v2.f32 {%0, %1}, [%2], %3;"
                 : "=f"(v.x), "=f"(v.y)
                 : "l"(p), "l"(pol));
    return v;
}

__global__ __launch_bounds__(kThreads, 8)
void embedding_bag_kernel(const float* __restrict__ weights,
                          const int* __restrict__ features,
                          float* __restrict__ out) {
    const int w = (blockIdx.x * kThreads + threadIdx.x) >> 5;
    const int lane = threadIdx.x & 31;

    // Table-grouped remap: warps [t*1024, (t+1)*1024) all pool table t.
    const int bag = ((w & 1023) << 5) | (w >> 10);
    const int table = w >> 10;  // == bag & 31

    // L2 evict-last policy for all gather lines (uniform -> UR expected).
    uint64_t pol;
    asm("createpolicy.fractional.L2::evict_last.b64 %0, 1.0;" : "=l"(pol));

    const int* __restrict__ idxp = features + bag * kL;

    // Coalesced index fetch: lane j holds draw j; lanes 0..17 also draw 32+j.
    const int i0 = __ldg(idxp + lane);
    const int i1 = (lane < kL - 32) ? __ldg(idxp + 32 + lane) : 0;

    // Base pointer into this bag's table slice, as float2.
    const float2* __restrict__ base =
        reinterpret_cast<const float2*>(weights) + (size_t)table * (kD / 2);
    constexpr size_t kRowStride2 = (size_t)kT * kD / 2;  // 1024 float2 per e

    float2 acc0 = make_float2(0.f, 0.f);
    float2 acc1 = make_float2(0.f, 0.f);

#pragma unroll
    for (int k = 0; k < 32; k += 2) {
        const int ia = __shfl_sync(0xffffffffu, i0, k);
        const int ib = __shfl_sync(0xffffffffu, i0, k + 1);
        const float2 va = ldg_policy_f2(base + (size_t)ia * kRowStride2 + lane, pol);
        const float2 vb = ldg_policy_f2(base + (size_t)ib * kRowStride2 + lane, pol);
        acc0.x += va.x; acc0.y += va.y;
        acc1.x += vb.x; acc1.y += vb.y;
    }
#pragma unroll
    for (int k = 0; k < 18; k += 2) {
        const int ia = __shfl_sync(0xffffffffu, i1, k);
        const int ib = __shfl_sync(0xffffffffu, i1, k + 1);
        const float2 va = ldg_policy_f2(base + (size_t)ia * kRowStride2 + lane, pol);
        const float2 vb = ldg_policy_f2(base + (size_t)ib * kRowStride2 + lane, pol);
        acc0.x += va.x; acc0.y += va.y;
        acc1.x += vb.x; acc1.y += vb.y;
    }

    float2 r;
    r.x = acc0.x + acc1.x;
    r.y = acc0.y + acc1.y;
    __stcs(reinterpret_cast<float2*>(out) + (size_t)bag * (kD / 2) + lane, r);
}

extern "C" void kernel_launch(void* const* d_in, const int* in_sizes, int n_in,
                              void* d_out, int out_size) {
    const float* weights  = (const float*)d_in[0];   // (E, T, D) fp32
    const int*   features = (const int*)d_in[1];     // (B*T*L,) int32
    // d_in[2]: offsets — uniform arange*L, folded into compile-time constants.
    float* out = (float*)d_out;                      // (B, T, D) fp32

    embedding_bag_kernel<<<kBlocks, kThreads>>>(weights, features, out);
}